// round 16
// baseline (speedup 1.0000x reference)
#include <cuda_runtime.h>
#include <cuda_fp16.h>
#include <math.h>

#define Bn 32
#define Ln 2048
#define Dn 1024
#define Un 512

#define TM 128
#define TN 128
#define KCH 64              // halfs per k-stage (128 B rows)
#define NST 3
#define NSTAGES (Dn / KCH)  // 16
#define STAGE_HALFS (TM * KCH)         // 8192
#define STAGE_BYTES (STAGE_HALFS * 2)  // 16384
#define BOFF (NST * STAGE_BYTES)       // 49152: B ring offset from A ring

// front_kernel grid partition
#define NCONV 16384   // 16384 blocks x 512 thr x 8 halfs = 64M halfs
#define NMISC 1024    // 1024 x 512 = 512K  (covers Un*Dn)

// static device scratch (no runtime allocation)
__device__ __align__(16) __half g_valsh[(size_t)Bn * Ln * Dn];  // fp16 values
__device__ __align__(16) __half g_wvTh[Un * Dn];                // fp16 Wv^T [u][k]
__device__ float g_ubias[Bn * Un];
__device__ float g_score[Bn * Ln];
__device__ float g_stat[Bn * 2];

__device__ __forceinline__ float tanh_fast(float x) {
    float y;
    asm("tanh.approx.f32 %0, %1;" : "=f"(y) : "f"(x));
    return y;
}

#define LDSM4(addr, r0_, r1_, r2_, r3_) \
    asm volatile("ldmatrix.sync.aligned.m8n8.x4.shared.b16 {%0,%1,%2,%3}, [%4];" \
                 : "=r"(r0_), "=r"(r1_), "=r"(r2_), "=r"(r3_) : "r"(addr))

#define CPA(dst, src) \
    asm volatile("cp.async.cg.shared.global [%0], [%1], 16;" ::"r"(dst), "l"(src))

// ---------------------------------------------------------------------------
// Launch 0 (fused front): values->fp16 | Wv^T fp16 + score init + out zero |
//                          per-batch prep.  Partitioned by blockIdx.x.
// ---------------------------------------------------------------------------
__global__ __launch_bounds__(512) void front_kernel(
    const float* __restrict__ values,
    const float* __restrict__ Wv,
    const float* __restrict__ mask,
    const float* __restrict__ vb,
    const float* __restrict__ query,
    const int*   __restrict__ tstep,
    const float* __restrict__ Wh,
    const float* __restrict__ bh,
    const float* __restrict__ bv,
    const float* __restrict__ Wp,
    const float* __restrict__ bp,
    const float* __restrict__ bm,
    float* __restrict__ out)
{
    int bid = blockIdx.x;
    int tid = threadIdx.x;

    if (bid < NCONV) {
        // ---- convert values -> fp16, 8 elems/thread ----
        size_t i = (size_t)bid * 512 + tid;
        const float4* src = (const float4*)values;
        float4 a = src[2 * i], b = src[2 * i + 1];
        union { uint4 u; __half2 h[4]; } o;
        o.h[0] = __floats2half2_rn(a.x, a.y);
        o.h[1] = __floats2half2_rn(a.z, a.w);
        o.h[2] = __floats2half2_rn(b.x, b.y);
        o.h[3] = __floats2half2_rn(b.z, b.w);
        reinterpret_cast<uint4*>(g_valsh)[i] = o.u;
        return;
    }
    if (bid < NCONV + NMISC) {
        // ---- misc: Wv^T, score init, out zero ----
        int i = (bid - NCONV) * 512 + tid;
        {
            int u = i >> 10, k = i & 1023;
            g_wvTh[i] = __float2half_rn(Wv[k * Un + u]);
        }
        if (i < Bn * Ln) g_score[i] = vb[0] + mask[i] * -1e9f;
        if (i < Bn * Dn) out[i] = 0.0f;
        return;
    }

    // ---- prep: one block per batch (deterministic) ----
    int b = bid - NCONV - NMISC;
    __shared__ float qs[Dn];
    __shared__ float red[512];
    __shared__ float s_loglen, s_logts;

    float cnt = 0.f;
    for (int l = tid; l < Ln; l += 512)
        cnt += (mask[b * Ln + l] == 0.0f) ? 1.0f : 0.0f;
    red[tid] = cnt;
    __syncthreads();
    for (int s = 256; s > 0; s >>= 1) {
        if (tid < s) red[tid] += red[tid + s];
        __syncthreads();
    }
    if (tid == 0) {
        s_loglen = __logf(1.0f + red[0]);
        int iv = tstep[0];
        float ts;
        if (iv >= 0 && iv < 1000000) ts = (float)iv;
        else ts = __int_as_float(iv);
        s_logts = __logf(1.0f + ts);
    }
    for (int d = tid; d < Dn; d += 512) qs[d] = query[b * Dn + d];
    __syncthreads();

    int u = tid;
    float acc = 0.f;
#pragma unroll 8
    for (int d = 0; d < Dn; d++) acc += qs[d] * Wh[d * Un + u];
    g_ubias[b * Un + u] = acc + bh[u] + bv[u] + bp[u] + bm[u]
                        + s_logts * Wp[u] + s_loglen * Wp[2 * Un + u];
}

// ---------------------------------------------------------------------------
// Launch 1 (profiled... index 1 now): fused score GEMM, fp16 m16n8k16,
//   k16-slice software pipeline, occ-1 (255-reg budget, no spills).
//   256 thr = 8 warps (2M x 4N); warp tile 64x32; TM=128, TN=128
// ---------------------------------------------------------------------------
__global__ __launch_bounds__(256, 1) void score_kernel(
    const float* __restrict__ Wp,
    const float* __restrict__ Wm,
    const float* __restrict__ vw,
    const float* __restrict__ prev)
{
    extern __shared__ char smraw[];
    float* eb    = (float*)(smraw + 2 * BOFF);
    float* prevs = eb + 8 * TN;
    unsigned As_u = (unsigned)__cvta_generic_to_shared(smraw);

    int tid = threadIdx.x, lane = tid & 31, warp = tid >> 5;
    int bb = blockIdx.z;
    int l0 = blockIdx.y * TM, u0 = blockIdx.x * TN;

    // cp.async addressing: one dst reg, two advancing src pointers
    int r0 = tid >> 3, c0 = tid & 7;
    unsigned dst0 = (unsigned)(r0 * 128 + 16 * (c0 ^ (r0 & 7)));
    const __half* srcA = g_valsh + (size_t)bb * Ln * Dn + (size_t)l0 * Dn
                       + (size_t)r0 * Dn + 8 * c0;
    const __half* srcB = g_wvTh + (size_t)u0 * Dn + (size_t)r0 * Dn + 8 * c0;

#define ISSUE(bufA) do { \
    _Pragma("unroll") \
    for (int i_ = 0; i_ < 4; i_++) { \
        CPA((bufA) + dst0 + 4096u * i_, srcA + (size_t)32 * i_ * Dn); \
        CPA((bufA) + BOFF + dst0 + 4096u * i_, srcB + (size_t)32 * i_ * Dn); \
    } } while (0)

    ISSUE(As_u);
    srcA += KCH; srcB += KCH;
    asm volatile("cp.async.commit_group;");
    ISSUE(As_u + STAGE_BYTES);
    srcA += KCH; srcB += KCH;
    asm volatile("cp.async.commit_group;");

    // epilogue staging — overlaps first cp.asyncs
    if (tid < TN) {
        eb[tid]          = g_ubias[bb * Un + u0 + tid];
        eb[TN + tid]     = Wp[Un + u0 + tid];
        eb[2 * TN + tid] = vw[u0 + tid];
#pragma unroll
        for (int j = 0; j < 5; j++) eb[(3 + j) * TN + tid] = Wm[j * Un + u0 + tid];
    }
    if (tid < TM + 4) {
        int gl = l0 - 2 + tid;
        prevs[tid] = (gl >= 0 && gl < Ln) ? prev[bb * Ln + gl] : 0.0f;
    }

    // ldmatrix base byte offsets (A mt: +2048*mt; B ntp: +2048*ntp; slice: ^32k)
    int lr = lane & 7, grp = lane >> 3;
    int rowadd = lr + 8 * (grp & 1);
    int cbase = grp >> 1;
    unsigned aoff0, boff0;
    {
        int rowA = (warp >> 2) * 64 + rowadd;
        aoff0 = (unsigned)(rowA * 128 + 16 * (cbase ^ (rowA & 7)));
        int rowB = (warp & 3) * 32 + rowadd;
        boff0 = (unsigned)(rowB * 128 + 16 * (cbase ^ (rowB & 7)));
    }

#define LOADF(fa, fb, buf, x) do { \
    LDSM4((buf) + BOFF + ((boff0 ^ (x))),          fb[0], fb[1], fb[2], fb[3]); \
    LDSM4((buf) + BOFF + ((boff0 ^ (x)) + 2048u),  fb[4], fb[5], fb[6], fb[7]); \
    LDSM4((buf) + (aoff0 ^ (x)),                   fa[0], fa[1], fa[2], fa[3]); \
    LDSM4((buf) + ((aoff0 ^ (x)) + 2048u),         fa[4], fa[5], fa[6], fa[7]); \
    LDSM4((buf) + ((aoff0 ^ (x)) + 4096u),         fa[8], fa[9], fa[10], fa[11]); \
    LDSM4((buf) + ((aoff0 ^ (x)) + 6144u),         fa[12], fa[13], fa[14], fa[15]); \
    } while (0)

    float acc[4][4][4];
#pragma unroll
    for (int a = 0; a < 4; a++)
#pragma unroll
        for (int n = 0; n < 4; n++)
#pragma unroll
            for (int c = 0; c < 4; c++) acc[a][n][c] = 0.f;

#define MMAF(fa, fb) do { \
    _Pragma("unroll") \
    for (int nt_ = 0; nt_ < 4; nt_++) { \
        unsigned b0_ = fb[(nt_ >> 1) * 4 + (nt_ & 1)]; \
        unsigned b1_ = fb[(nt_ >> 1) * 4 + (nt_ & 1) + 2]; \
        _Pragma("unroll") \
        for (int mt_ = 0; mt_ < 4; mt_++) { \
            asm volatile( \
                "mma.sync.aligned.m16n8k16.row.col.f32.f16.f16.f32 " \
                "{%0,%1,%2,%3}, {%4,%5,%6,%7}, {%8,%9}, {%0,%1,%2,%3};" \
                : "+f"(acc[mt_][nt_][0]), "+f"(acc[mt_][nt_][1]), \
                  "+f"(acc[mt_][nt_][2]), "+f"(acc[mt_][nt_][3]) \
                : "r"(fa[mt_ * 4]), "r"(fa[mt_ * 4 + 1]), \
                  "r"(fa[mt_ * 4 + 2]), "r"(fa[mt_ * 4 + 3]), \
                  "r"(b0_), "r"(b1_)); \
        } } } while (0)

    unsigned f0a[16], f0b[8], f1a[16], f1b[8];

    // stage 0 ready: own-wait THEN barrier (all threads' copies visible)
    asm volatile("cp.async.wait_group 1;");
    __syncthreads();

    unsigned bufC = As_u;
    LOADF(f0a, f0b, bufC, 0u);

#pragma unroll 1
    for (int s = 0; s < NSTAGES; s++) {
        LOADF(f1a, f1b, bufC, 32u);
        MMAF(f0a, f0b);
        LOADF(f0a, f0b, bufC, 64u);
        MMAF(f1a, f1b);
        LOADF(f1a, f1b, bufC, 96u);
        MMAF(f0a, f0b);
        if (s + 1 < NSTAGES) {
            unsigned bufI = (bufC == As_u) ? As_u + 2 * STAGE_BYTES
                                           : bufC - STAGE_BYTES;
            unsigned bufN = (bufC == As_u + 2 * STAGE_BYTES) ? As_u
                                                             : bufC + STAGE_BYTES;
            // issue prefetch, commit, wait own group, THEN barrier,
            // THEN read next stage (all threads' copies visible).
            if (s + 2 < NSTAGES) {
                ISSUE(bufI);
                srcA += KCH; srcB += KCH;
            }
            asm volatile("cp.async.commit_group;");
            asm volatile("cp.async.wait_group 1;");
            __syncthreads();
            LOADF(f0a, f0b, bufN, 0u);
            bufC = bufN;
        }
        MMAF(f1a, f1b);
    }

    // ---- epilogue ----
    int qa = lane & 3, rr = lane >> 2;
    int warpM = warp >> 2, warpN = warp & 3;
#pragma unroll
    for (int mt = 0; mt < 4; mt++) {
#pragma unroll
        for (int half = 0; half < 2; half++) {
            int rl = warpM * 64 + mt * 16 + rr + 8 * half;
            float ll = __logf(2.0f + (float)(l0 + rl));
            float sumv = 0.f;
#pragma unroll
            for (int nt = 0; nt < 4; nt++) {
#pragma unroll
                for (int j = 0; j < 2; j++) {
                    int col = warpN * 32 + nt * 8 + qa * 2 + j;
                    float sc = acc[mt][nt][half * 2 + j] + eb[col] + ll * eb[TN + col];
#pragma unroll
                    for (int w = 0; w < 5; w++)
                        sc += prevs[rl + w] * eb[(3 + w) * TN + col];
                    sumv += tanh_fast(sc) * eb[2 * TN + col];
                }
            }
            sumv += __shfl_xor_sync(0xffffffffu, sumv, 1);
            sumv += __shfl_xor_sync(0xffffffffu, sumv, 2);
            if (qa == 0) atomicAdd(&g_score[bb * Ln + l0 + rl], sumv);
        }
    }
}

// ---------------------------------------------------------------------------
// Launch 2: per-batch softmax stats (max, 1/sum)
// ---------------------------------------------------------------------------
__global__ __launch_bounds__(1024) void stats_kernel()
{
    int b = blockIdx.x;
    int tid = threadIdx.x;   // 1024
    __shared__ float red[1024];
    __shared__ float s_max;

    float m = fmaxf(g_score[b * Ln + tid], g_score[b * Ln + 1024 + tid]);
    red[tid] = m;
    __syncthreads();
    for (int s = 512; s > 0; s >>= 1) {
        if (tid < s) red[tid] = fmaxf(red[tid], red[tid + s]);
        __syncthreads();
    }
    if (tid == 0) s_max = red[0];
    __syncthreads();

    float sum = __expf(g_score[b * Ln + tid] - s_max)
              + __expf(g_score[b * Ln + 1024 + tid] - s_max);
    red[tid] = sum;
    __syncthreads();
    for (int s = 512; s > 0; s >>= 1) {
        if (tid < s) red[tid] += red[tid + s];
        __syncthreads();
    }
    if (tid == 0) {
        g_stat[2 * b] = s_max;
        g_stat[2 * b + 1] = 1.0f / red[0];
    }
}

// ---------------------------------------------------------------------------
// Launch 3: fused attn-write + context accumulate
// ---------------------------------------------------------------------------
__global__ __launch_bounds__(512) void context_kernel(float* __restrict__ out)
{
    int lc = blockIdx.x;    // 16 chunks of 128 rows
    int b  = blockIdx.y;    // 32
    int tid = threadIdx.x;  // 512 half2 cols
    __shared__ float watt[128];

    float smax = g_stat[2 * b], sinv = g_stat[2 * b + 1];
    if (tid < 128) {
        float w = __expf(g_score[b * Ln + lc * 128 + tid] - smax) * sinv;
        watt[tid] = w;
        out[Bn * Dn + b * Ln + lc * 128 + tid] = w;
    }
    __syncthreads();

    const __half2* v = reinterpret_cast<const __half2*>(g_valsh)
                     + ((size_t)b * Ln + (size_t)lc * 128) * (Dn / 2) + tid;
    float ax = 0.f, ay = 0.f;
#pragma unroll 8
    for (int l = 0; l < 128; l++) {
        float2 f = __half22float2(v[(size_t)l * (Dn / 2)]);
        ax += watt[l] * f.x;
        ay += watt[l] * f.y;
    }
    atomicAdd(&out[b * Dn + 2 * tid], ax);
    atomicAdd(&out[b * Dn + 2 * tid + 1], ay);
}

// ---------------------------------------------------------------------------
extern "C" void kernel_launch(void* const* d_in, const int* in_sizes, int n_in,
                              void* d_out, int out_size)
{
    const float* query = (const float*)d_in[0];
    const float* values = (const float*)d_in[1];
    const float* mask = (const float*)d_in[2];
    const float* prev = (const float*)d_in[3];
    const int*   tstep = (const int*)d_in[4];
    const float* Wh = (const float*)d_in[5];
    const float* bh = (const float*)d_in[6];
    const float* Wv = (const float*)d_in[7];
    const float* bv = (const float*)d_in[8];
    const float* Wp = (const float*)d_in[9];
    const float* bp = (const float*)d_in[10];
    const float* Wm = (const float*)d_in[11];
    const float* bm = (const float*)d_in[12];
    const float* vw = (const float*)d_in[13];
    const float* vb = (const float*)d_in[14];
    float* out = (float*)d_out;

    const int smem_bytes = 2 * BOFF + (8 * TN + TM + 8) * 4;
    cudaFuncSetAttribute(score_kernel,
                         cudaFuncAttributeMaxDynamicSharedMemorySize, smem_bytes);

    front_kernel<<<NCONV + NMISC + Bn, 512>>>(values, Wv, mask, vb, query,
                                              tstep, Wh, bh, bv, Wp, bp, bm, out);
    dim3 gs(Un / TN, Ln / TM, Bn);
    score_kernel<<<gs, 256, smem_bytes>>>(Wp, Wm, vw, prev);
    stats_kernel<<<Bn, 1024>>>();
    context_kernel<<<dim3(16, Bn), 512>>>(out);
}

// round 17
// speedup vs baseline: 1.0473x; 1.0473x over previous
#include <cuda_runtime.h>
#include <cuda_fp16.h>
#include <math.h>

#define Bn 32
#define Ln 2048
#define Dn 1024
#define Un 512

#define TM 128
#define TN 128
#define KCH 64              // halfs per k-stage (128 B rows)
#define NST 3
#define NSTAGES (Dn / KCH)  // 16
#define STAGE_HALFS (TM * KCH)         // 8192
#define STAGE_BYTES (STAGE_HALFS * 2)  // 16384
#define BOFF (NST * STAGE_BYTES)       // 49152: B ring offset from A ring

// front_kernel grid partition
#define NCONV 16384   // 16384 blocks x 512 thr x 8 halfs = 64M halfs
#define NMISC 1024    // 1024 x 512 = 512K  (covers Un*Dn)

// static device scratch (no runtime allocation)
__device__ __align__(16) __half g_valsh[(size_t)Bn * Ln * Dn];  // fp16 values
__device__ __align__(16) __half g_wvTh[Un * Dn];                // fp16 Wv^T [u][k]
__device__ float g_ubias[Bn * Un];
__device__ float g_score[Bn * Ln];
__device__ float g_stat[Bn * 2];

__device__ __forceinline__ float tanh_fast(float x) {
    float y;
    asm("tanh.approx.f32 %0, %1;" : "=f"(y) : "f"(x));
    return y;
}

#define LDSM4(addr, r0_, r1_, r2_, r3_) \
    asm volatile("ldmatrix.sync.aligned.m8n8.x4.shared.b16 {%0,%1,%2,%3}, [%4];" \
                 : "=r"(r0_), "=r"(r1_), "=r"(r2_), "=r"(r3_) : "r"(addr))

#define CPA(dst, src) \
    asm volatile("cp.async.cg.shared.global [%0], [%1], 16;" ::"r"(dst), "l"(src))

// ---------------------------------------------------------------------------
// Launch 0 (fused front): values->fp16 | Wv^T fp16 + score init + out zero |
//                          per-batch prep.  Partitioned by blockIdx.x.
// ---------------------------------------------------------------------------
__global__ __launch_bounds__(512) void front_kernel(
    const float* __restrict__ values,
    const float* __restrict__ Wv,
    const float* __restrict__ mask,
    const float* __restrict__ vb,
    const float* __restrict__ query,
    const int*   __restrict__ tstep,
    const float* __restrict__ Wh,
    const float* __restrict__ bh,
    const float* __restrict__ bv,
    const float* __restrict__ Wp,
    const float* __restrict__ bp,
    const float* __restrict__ bm,
    float* __restrict__ out)
{
    int bid = blockIdx.x;
    int tid = threadIdx.x;

    if (bid < NCONV) {
        // ---- convert values -> fp16, 8 elems/thread ----
        size_t i = (size_t)bid * 512 + tid;
        const float4* src = (const float4*)values;
        float4 a = src[2 * i], b = src[2 * i + 1];
        union { uint4 u; __half2 h[4]; } o;
        o.h[0] = __floats2half2_rn(a.x, a.y);
        o.h[1] = __floats2half2_rn(a.z, a.w);
        o.h[2] = __floats2half2_rn(b.x, b.y);
        o.h[3] = __floats2half2_rn(b.z, b.w);
        reinterpret_cast<uint4*>(g_valsh)[i] = o.u;
        return;
    }
    if (bid < NCONV + NMISC) {
        // ---- misc: Wv^T, score init, out zero ----
        int i = (bid - NCONV) * 512 + tid;
        {
            int u = i >> 10, k = i & 1023;
            g_wvTh[i] = __float2half_rn(Wv[k * Un + u]);
        }
        if (i < Bn * Ln) g_score[i] = vb[0] + mask[i] * -1e9f;
        if (i < Bn * Dn) out[i] = 0.0f;
        return;
    }

    // ---- prep: one block per batch (deterministic) ----
    int b = bid - NCONV - NMISC;
    __shared__ float qs[Dn];
    __shared__ float red[512];
    __shared__ float s_loglen, s_logts;

    float cnt = 0.f;
    for (int l = tid; l < Ln; l += 512)
        cnt += (mask[b * Ln + l] == 0.0f) ? 1.0f : 0.0f;
    red[tid] = cnt;
    __syncthreads();
    for (int s = 256; s > 0; s >>= 1) {
        if (tid < s) red[tid] += red[tid + s];
        __syncthreads();
    }
    if (tid == 0) {
        s_loglen = __logf(1.0f + red[0]);
        int iv = tstep[0];
        float ts;
        if (iv >= 0 && iv < 1000000) ts = (float)iv;
        else ts = __int_as_float(iv);
        s_logts = __logf(1.0f + ts);
    }
    for (int d = tid; d < Dn; d += 512) qs[d] = query[b * Dn + d];
    __syncthreads();

    int u = tid;
    float acc = 0.f;
#pragma unroll 8
    for (int d = 0; d < Dn; d++) acc += qs[d] * Wh[d * Un + u];
    g_ubias[b * Un + u] = acc + bh[u] + bv[u] + bp[u] + bm[u]
                        + s_logts * Wp[u] + s_loglen * Wp[2 * Un + u];
}

// ---------------------------------------------------------------------------
// Launch 1: fused score GEMM, fp16 m16n8k16, ldmatrix, k16-slice pipeline,
//   occ-2 (restored R15 config). 256 thr = 8 warps (2M x 4N); TM=128, TN=128
// ---------------------------------------------------------------------------
__global__ __launch_bounds__(256, 2) void score_kernel(
    const float* __restrict__ Wp,
    const float* __restrict__ Wm,
    const float* __restrict__ vw,
    const float* __restrict__ prev)
{
    extern __shared__ char smraw[];
    float* eb    = (float*)(smraw + 2 * BOFF);
    float* prevs = eb + 8 * TN;
    unsigned As_u = (unsigned)__cvta_generic_to_shared(smraw);

    int tid = threadIdx.x, lane = tid & 31, warp = tid >> 5;
    int bb = blockIdx.z;
    int l0 = blockIdx.y * TM, u0 = blockIdx.x * TN;

    // cp.async addressing: one dst reg, two advancing src pointers
    int r0 = tid >> 3, c0 = tid & 7;
    unsigned dst0 = (unsigned)(r0 * 128 + 16 * (c0 ^ (r0 & 7)));
    const __half* srcA = g_valsh + (size_t)bb * Ln * Dn + (size_t)l0 * Dn
                       + (size_t)r0 * Dn + 8 * c0;
    const __half* srcB = g_wvTh + (size_t)u0 * Dn + (size_t)r0 * Dn + 8 * c0;

#define ISSUE(bufA) do { \
    _Pragma("unroll") \
    for (int i_ = 0; i_ < 4; i_++) { \
        CPA((bufA) + dst0 + 4096u * i_, srcA + (size_t)32 * i_ * Dn); \
        CPA((bufA) + BOFF + dst0 + 4096u * i_, srcB + (size_t)32 * i_ * Dn); \
    } } while (0)

    ISSUE(As_u);
    srcA += KCH; srcB += KCH;
    asm volatile("cp.async.commit_group;");
    ISSUE(As_u + STAGE_BYTES);
    srcA += KCH; srcB += KCH;
    asm volatile("cp.async.commit_group;");

    // epilogue staging — overlaps first cp.asyncs
    if (tid < TN) {
        eb[tid]          = g_ubias[bb * Un + u0 + tid];
        eb[TN + tid]     = Wp[Un + u0 + tid];
        eb[2 * TN + tid] = vw[u0 + tid];
#pragma unroll
        for (int j = 0; j < 5; j++) eb[(3 + j) * TN + tid] = Wm[j * Un + u0 + tid];
    }
    if (tid < TM + 4) {
        int gl = l0 - 2 + tid;
        prevs[tid] = (gl >= 0 && gl < Ln) ? prev[bb * Ln + gl] : 0.0f;
    }

    // ldmatrix base byte offsets (A mt: +2048*mt; B ntp: +2048*ntp; slice: ^32k)
    int lr = lane & 7, grp = lane >> 3;
    int rowadd = lr + 8 * (grp & 1);
    int cbase = grp >> 1;
    unsigned aoff0, boff0;
    {
        int rowA = (warp >> 2) * 64 + rowadd;
        aoff0 = (unsigned)(rowA * 128 + 16 * (cbase ^ (rowA & 7)));
        int rowB = (warp & 3) * 32 + rowadd;
        boff0 = (unsigned)(rowB * 128 + 16 * (cbase ^ (rowB & 7)));
    }

#define LOADF(fa, fb, buf, x) do { \
    LDSM4((buf) + BOFF + ((boff0 ^ (x))),          fb[0], fb[1], fb[2], fb[3]); \
    LDSM4((buf) + BOFF + ((boff0 ^ (x)) + 2048u),  fb[4], fb[5], fb[6], fb[7]); \
    LDSM4((buf) + (aoff0 ^ (x)),                   fa[0], fa[1], fa[2], fa[3]); \
    LDSM4((buf) + ((aoff0 ^ (x)) + 2048u),         fa[4], fa[5], fa[6], fa[7]); \
    LDSM4((buf) + ((aoff0 ^ (x)) + 4096u),         fa[8], fa[9], fa[10], fa[11]); \
    LDSM4((buf) + ((aoff0 ^ (x)) + 6144u),         fa[12], fa[13], fa[14], fa[15]); \
    } while (0)

    float acc[4][4][4];
#pragma unroll
    for (int a = 0; a < 4; a++)
#pragma unroll
        for (int n = 0; n < 4; n++)
#pragma unroll
            for (int c = 0; c < 4; c++) acc[a][n][c] = 0.f;

#define MMAF(fa, fb) do { \
    _Pragma("unroll") \
    for (int nt_ = 0; nt_ < 4; nt_++) { \
        unsigned b0_ = fb[(nt_ >> 1) * 4 + (nt_ & 1)]; \
        unsigned b1_ = fb[(nt_ >> 1) * 4 + (nt_ & 1) + 2]; \
        _Pragma("unroll") \
        for (int mt_ = 0; mt_ < 4; mt_++) { \
            asm volatile( \
                "mma.sync.aligned.m16n8k16.row.col.f32.f16.f16.f32 " \
                "{%0,%1,%2,%3}, {%4,%5,%6,%7}, {%8,%9}, {%0,%1,%2,%3};" \
                : "+f"(acc[mt_][nt_][0]), "+f"(acc[mt_][nt_][1]), \
                  "+f"(acc[mt_][nt_][2]), "+f"(acc[mt_][nt_][3]) \
                : "r"(fa[mt_ * 4]), "r"(fa[mt_ * 4 + 1]), \
                  "r"(fa[mt_ * 4 + 2]), "r"(fa[mt_ * 4 + 3]), \
                  "r"(b0_), "r"(b1_)); \
        } } } while (0)

    unsigned f0a[16], f0b[8], f1a[16], f1b[8];

    // stage 0 ready: own-wait THEN barrier (all threads' copies visible)
    asm volatile("cp.async.wait_group 1;");
    __syncthreads();

    unsigned bufC = As_u;
    LOADF(f0a, f0b, bufC, 0u);

#pragma unroll 1
    for (int s = 0; s < NSTAGES; s++) {
        LOADF(f1a, f1b, bufC, 32u);
        MMAF(f0a, f0b);
        LOADF(f0a, f0b, bufC, 64u);
        MMAF(f1a, f1b);
        LOADF(f1a, f1b, bufC, 96u);
        MMAF(f0a, f0b);
        if (s + 1 < NSTAGES) {
            unsigned bufI = (bufC == As_u) ? As_u + 2 * STAGE_BYTES
                                           : bufC - STAGE_BYTES;
            unsigned bufN = (bufC == As_u + 2 * STAGE_BYTES) ? As_u
                                                             : bufC + STAGE_BYTES;
            // issue prefetch, commit, wait own group, THEN barrier,
            // THEN read next stage (all threads' copies visible).
            if (s + 2 < NSTAGES) {
                ISSUE(bufI);
                srcA += KCH; srcB += KCH;
            }
            asm volatile("cp.async.commit_group;");
            asm volatile("cp.async.wait_group 1;");
            __syncthreads();
            LOADF(f0a, f0b, bufN, 0u);
            bufC = bufN;
        }
        MMAF(f1a, f1b);
    }

    // ---- epilogue ----
    int qa = lane & 3, rr = lane >> 2;
    int warpM = warp >> 2, warpN = warp & 3;
#pragma unroll
    for (int mt = 0; mt < 4; mt++) {
#pragma unroll
        for (int half = 0; half < 2; half++) {
            int rl = warpM * 64 + mt * 16 + rr + 8 * half;
            float ll = __logf(2.0f + (float)(l0 + rl));
            float sumv = 0.f;
#pragma unroll
            for (int nt = 0; nt < 4; nt++) {
#pragma unroll
                for (int j = 0; j < 2; j++) {
                    int col = warpN * 32 + nt * 8 + qa * 2 + j;
                    float sc = acc[mt][nt][half * 2 + j] + eb[col] + ll * eb[TN + col];
#pragma unroll
                    for (int w = 0; w < 5; w++)
                        sc += prevs[rl + w] * eb[(3 + w) * TN + col];
                    sumv += tanh_fast(sc) * eb[2 * TN + col];
                }
            }
            sumv += __shfl_xor_sync(0xffffffffu, sumv, 1);
            sumv += __shfl_xor_sync(0xffffffffu, sumv, 2);
            if (qa == 0) atomicAdd(&g_score[bb * Ln + l0 + rl], sumv);
        }
    }
}

// ---------------------------------------------------------------------------
// Launch 2: per-batch softmax stats (max, 1/sum)
// ---------------------------------------------------------------------------
__global__ __launch_bounds__(1024) void stats_kernel()
{
    int b = blockIdx.x;
    int tid = threadIdx.x;   // 1024
    __shared__ float red[1024];
    __shared__ float s_max;

    float m = fmaxf(g_score[b * Ln + tid], g_score[b * Ln + 1024 + tid]);
    red[tid] = m;
    __syncthreads();
    for (int s = 512; s > 0; s >>= 1) {
        if (tid < s) red[tid] = fmaxf(red[tid], red[tid + s]);
        __syncthreads();
    }
    if (tid == 0) s_max = red[0];
    __syncthreads();

    float sum = __expf(g_score[b * Ln + tid] - s_max)
              + __expf(g_score[b * Ln + 1024 + tid] - s_max);
    red[tid] = sum;
    __syncthreads();
    for (int s = 512; s > 0; s >>= 1) {
        if (tid < s) red[tid] += red[tid + s];
        __syncthreads();
    }
    if (tid == 0) {
        g_stat[2 * b] = s_max;
        g_stat[2 * b + 1] = 1.0f / red[0];
    }
}

// ---------------------------------------------------------------------------
// Launch 3: fused attn-write + context accumulate
// ---------------------------------------------------------------------------
__global__ __launch_bounds__(512) void context_kernel(float* __restrict__ out)
{
    int lc = blockIdx.x;    // 16 chunks of 128 rows
    int b  = blockIdx.y;    // 32
    int tid = threadIdx.x;  // 512 half2 cols
    __shared__ float watt[128];

    float smax = g_stat[2 * b], sinv = g_stat[2 * b + 1];
    if (tid < 128) {
        float w = __expf(g_score[b * Ln + lc * 128 + tid] - smax) * sinv;
        watt[tid] = w;
        out[Bn * Dn + b * Ln + lc * 128 + tid] = w;
    }
    __syncthreads();

    const __half2* v = reinterpret_cast<const __half2*>(g_valsh)
                     + ((size_t)b * Ln + (size_t)lc * 128) * (Dn / 2) + tid;
    float ax = 0.f, ay = 0.f;
#pragma unroll 8
    for (int l = 0; l < 128; l++) {
        float2 f = __half22float2(v[(size_t)l * (Dn / 2)]);
        ax += watt[l] * f.x;
        ay += watt[l] * f.y;
    }
    atomicAdd(&out[b * Dn + 2 * tid], ax);
    atomicAdd(&out[b * Dn + 2 * tid + 1], ay);
}

// ---------------------------------------------------------------------------
extern "C" void kernel_launch(void* const* d_in, const int* in_sizes, int n_in,
                              void* d_out, int out_size)
{
    const float* query = (const float*)d_in[0];
    const float* values = (const float*)d_in[1];
    const float* mask = (const float*)d_in[2];
    const float* prev = (const float*)d_in[3];
    const int*   tstep = (const int*)d_in[4];
    const float* Wh = (const float*)d_in[5];
    const float* bh = (const float*)d_in[6];
    const float* Wv = (const float*)d_in[7];
    const float* bv = (const float*)d_in[8];
    const float* Wp = (const float*)d_in[9];
    const float* bp = (const float*)d_in[10];
    const float* Wm = (const float*)d_in[11];
    const float* bm = (const float*)d_in[12];
    const float* vw = (const float*)d_in[13];
    const float* vb = (const float*)d_in[14];
    float* out = (float*)d_out;

    const int smem_bytes = 2 * BOFF + (8 * TN + TM + 8) * 4;
    cudaFuncSetAttribute(score_kernel,
                         cudaFuncAttributeMaxDynamicSharedMemorySize, smem_bytes);

    front_kernel<<<NCONV + NMISC + Bn, 512>>>(values, Wv, mask, vb, query,
                                              tstep, Wh, bh, bv, Wp, bp, bm, out);
    dim3 gs(Un / TN, Ln / TM, Bn);
    score_kernel<<<gs, 256, smem_bytes>>>(Wp, Wm, vw, prev);
    stats_kernel<<<Bn, 1024>>>();
    context_kernel<<<dim3(16, Bn), 512>>>(out);
}